// round 12
// baseline (speedup 1.0000x reference)
#include <cuda_runtime.h>
#include <cuda_bf16.h>
#include <math.h>

// Fixed shapes
#define B_ 32
#define C_ 6
#define T_ 64
#define K_ 8
#define N_ 128
#define NSEG 1016
#define NSEGP 1024
#define NSEGP2 512             // segment pairs
#define NCL 2048
#define NCLP2 1024             // candidate pairs
#define EPS_ 1e-6f
#define THRESH_ 0.5f
#define PAD_ 1e9f

#define THREADS 256
#define WARPS 8                // each warp = independent point group
#define M 4                    // points per warp
#define PTS_BLK (WARPS * M)    // 32
#define HALVES (T_ / PTS_BLK)  // 2
// grid = B*C*HALVES = 384

typedef unsigned long long u64;

__device__ float    g_scratch[B_ * C_ * 2];   // zero-init (.bss)
__device__ unsigned g_tick[B_ * C_];          // zero-init, reset after use

__device__ __forceinline__ u64 F2ADD(u64 a, u64 b) {
    u64 d; asm("add.rn.f32x2 %0,%1,%2;" : "=l"(d) : "l"(a), "l"(b)); return d;
}
__device__ __forceinline__ u64 F2SUB(u64 a, u64 b) {
    u64 d; asm("sub.rn.f32x2 %0,%1,%2;" : "=l"(d) : "l"(a), "l"(b)); return d;
}
__device__ __forceinline__ u64 F2MUL(u64 a, u64 b) {
    u64 d; asm("mul.rn.f32x2 %0,%1,%2;" : "=l"(d) : "l"(a), "l"(b)); return d;
}
__device__ __forceinline__ u64 F2FMA(u64 a, u64 b, u64 c) {
    u64 d; asm("fma.rn.f32x2 %0,%1,%2,%3;" : "=l"(d) : "l"(a), "l"(b), "l"(c)); return d;
}
__device__ __forceinline__ u64 F2PK(float lo, float hi) {
    u64 d; asm("mov.b64 %0,{%1,%2};" : "=l"(d) : "f"(lo), "f"(hi)); return d;
}
__device__ __forceinline__ void F2UP(u64 a, float& lo, float& hi) {
    asm("mov.b64 {%0,%1},%2;" : "=f"(lo), "=f"(hi) : "l"(a));
}
__device__ __forceinline__ float frcp(float x) {
    float r; asm("rcp.approx.f32 %0,%1;" : "=f"(r) : "f"(x)); return r;
}

__global__ __launch_bounds__(THREADS, 3)
void offroad_kernel(const float* __restrict__ points,
                    const float* __restrict__ road_boundary,
                    const float* __restrict__ centerlines,
                    float* __restrict__ out) {
    // Segment-PAIR packed: entry i covers segments (2i, 2i+1)
    __shared__ float4 sA2[NSEGP2];   // (-ax0,-ax1,-ay0,-ay1)
    __shared__ float4 sD2[NSEGP2];   // (-dx0,-dx1,-dy0,-dy1)
    __shared__ float4 sCl[NCLP2];    // (-qx0,-qx1,-qy0,-qy1) per cand pair
    __shared__ float2 sClh[NCLP2];   // (h0,h1) = 0.5*|q|^2 per pair
    __shared__ float  sVal[WARPS];

    const int bid = blockIdx.x;
    const int half = bid & 1;
    const int c = (bid >> 1) % C_;
    const int b = bid / (2 * C_);
    const int idx = b * C_ + c;
    const int tid = threadIdx.x;

    // ---- fill segment pairs (padded with far-away inert unit segments) ----
    {
        const float2* rb = (const float2*)road_boundary + (size_t)b * K_ * N_;
        #pragma unroll
        for (int p0 = 0; p0 < NSEGP2; p0 += THREADS) {
            int pi = p0 + tid;
            float nax[2], nay[2], ndx[2], ndy[2];
            #pragma unroll
            for (int h = 0; h < 2; h++) {
                int s = 2 * pi + h;
                if (s < NSEG) {
                    int k = s / (N_ - 1);
                    int j = s - k * (N_ - 1);
                    float2 a = rb[k * N_ + j];
                    float2 e = rb[k * N_ + j + 1];
                    nax[h] = -a.x; nay[h] = -a.y;
                    ndx[h] = a.x - e.x; ndy[h] = a.y - e.y;
                } else {
                    nax[h] = -PAD_; nay[h] = -PAD_;  // a=(PAD,PAD), d=(1,0): inert
                    ndx[h] = -1.0f; ndy[h] = 0.0f;
                }
            }
            sA2[pi] = make_float4(nax[0], nax[1], nay[0], nay[1]);
            sD2[pi] = make_float4(ndx[0], ndx[1], ndy[0], ndy[1]);
        }
    }
    // ---- fill centerlines (negated pair-SoA + half-norms) ----
    {
        const float4* cl4 = (const float4*)(centerlines + (size_t)b * NCL * 2);
        #pragma unroll
        for (int p0 = 0; p0 < NCLP2; p0 += THREADS) {
            int pi = p0 + tid;
            float4 v = cl4[pi];     // (q0x,q0y,q1x,q1y)
            sCl[pi] = make_float4(-v.x, -v.z, -v.y, -v.w);
            sClh[pi] = make_float2(0.5f * fmaf(v.x, v.x, v.y * v.y),
                                   0.5f * fmaf(v.z, v.z, v.w * v.w));
        }
    }
    __syncthreads();

    const int w = tid >> 5;     // warp = point group (0..7)
    const int l = tid & 31;

    float px[M], py[M];
    {
        const float2* pp = (const float2*)points +
            ((size_t)idx) * T_ + half * PTS_BLK + w * M;
        #pragma unroll
        for (int j = 0; j < M; j++) { float2 p = pp[j]; px[j] = p.x; py[j] = p.y; }
    }

    // point-duplicated packed constants (used by both phases)
    u64 pxd[M], pyd[M];
    #pragma unroll
    for (int j = 0; j < M; j++) { pxd[j] = F2PK(px[j], px[j]); pyd[j] = F2PK(py[j], py[j]); }

    // ---- Phase A: argmin over candidate pairs (score = 0.5|q|^2 - p.q) ----
    float sc[M]; int bp[M];
    #pragma unroll
    for (int j = 0; j < M; j++) { sc[j] = 3.4e38f; bp[j] = 0; }

    const u64* clh64 = (const u64*)sClh;
    #pragma unroll 8
    for (int it = 0; it < NCLP2 / 32; it++) {       // 32 iters
        int pi = l + it * 32;
        float4 nq = sCl[pi];
        u64 h2  = clh64[pi];
        u64 nqx = F2PK(nq.x, nq.y);
        u64 nqy = F2PK(nq.z, nq.w);
        #pragma unroll
        for (int j = 0; j < M; j++) {
            u64 s2 = F2FMA(pxd[j], nqx, F2FMA(pyd[j], nqy, h2));
            float s0, s1; F2UP(s2, s0, s1);
            float pmin = fminf(s0, s1);
            if (pmin < sc[j]) { sc[j] = pmin; bp[j] = pi; }
        }
    }
    #pragma unroll
    for (int off = 16; off; off >>= 1) {
        #pragma unroll
        for (int j = 0; j < M; j++) {
            float os = __shfl_xor_sync(0xffffffffu, sc[j], off);
            int   oi = __shfl_xor_sync(0xffffffffu, bp[j], off);
            if (os < sc[j] || (os == sc[j] && oi < bp[j])) { sc[j] = os; bp[j] = oi; }
        }
    }
    // resolve which half of the winning pair
    u64 daxd[M], ndayd[M];
    #pragma unroll
    for (int j = 0; j < M; j++) {
        float4 nq = sCl[bp[j]];         // broadcast
        u64 h2 = clh64[bp[j]];
        u64 s2 = F2FMA(pxd[j], F2PK(nq.x, nq.y),
                 F2FMA(pyd[j], F2PK(nq.z, nq.w), h2));
        float s0, s1; F2UP(s2, s0, s1);
        bool h1 = (s1 < s0);            // tie -> half 0 (lower index)
        float nqx = h1 ? nq.y : nq.x;
        float nqy = h1 ? nq.w : nq.z;
        float dax = -nqx - px[j];       // qx - px
        float day = -nqy - py[j];
        daxd[j]  = F2PK(dax, dax);
        ndayd[j] = F2PK(-day, -day);
    }
    const u64 neps2 = F2PK(-EPS_, -EPS_);
    const u64 eps2p = F2PK(EPS_, EPS_);

    // ---- Phase B: fused distance + intersection, 2 segments per iteration ----
    float mind2[M];
    u64 hbits[M];
    #pragma unroll
    for (int j = 0; j < M; j++) { mind2[j] = 3.4e38f; hbits[j] = 0ull; }

    #pragma unroll 8
    for (int it = 0; it < NSEGP2 / 32; it++) {      // 16 iters (2 segs each)
        int pi = l + it * 32;
        float4 A = sA2[pi];
        float4 D = sD2[pi];
        u64 naxp = F2PK(A.x, A.y), nayp = F2PK(A.z, A.w);
        u64 ndxp = F2PK(D.x, D.y), ndyp = F2PK(D.z, D.w);
        u64 len2p = F2FMA(ndxp, ndxp, F2FMA(ndyp, ndyp, eps2p));
        float le0, le1; F2UP(len2p, le0, le1);
        float negr0 = -frcp(le0);
        float negr1 = -frcp(le1);
        #pragma unroll
        for (int j = 0; j < M; j++) {
            u64 v1x = F2ADD(pxd[j], naxp);          // p - a (2 segs)
            u64 v1y = F2ADD(pyd[j], nayp);
            u64 ndt = F2FMA(v1y, ndyp, F2MUL(v1x, ndxp));   // -(v1.d)
            float n0, n1; F2UP(ndt, n0, n1);
            float p0 = __saturatef(n0 * negr0);     // FMUL.SAT
            float p1 = __saturatef(n1 * negr1);
            u64 pr = F2PK(p0, p1);
            u64 ex = F2FMA(ndxp, pr, v1x);          // v1x - dx*pr
            u64 ey = F2FMA(ndyp, pr, v1y);
            u64 d2 = F2FMA(ey, ey, F2MUL(ex, ex));
            float d20, d21; F2UP(d2, d20, d21);
            mind2[j] = fminf(mind2[j], fminf(d20, d21));
            // nw = -(cross(da,db)+eps); c1 = cross(da,v1); c2 = cross(db,v1)
            u64 nw = F2FMA(ndayd[j], ndxp, F2FMA(daxd[j], ndyp, neps2));
            u64 c1 = F2FMA(daxd[j], v1y, F2MUL(ndayd[j], v1x));
            u64 c2 = F2SUB(F2MUL(ndyp, v1x), F2MUL(ndxp, v1y));
            u64 s1 = F2MUL(c1, F2ADD(c1, nw));      // half-hit iff sign set
            u64 s2 = F2MUL(c2, F2ADD(c2, nw));
            hbits[j] |= (s1 & s2);                  // LOP3 sign-AND, OR-accumulate
        }
    }
    #pragma unroll
    for (int off = 16; off; off >>= 1) {
        #pragma unroll
        for (int j = 0; j < M; j++) {
            mind2[j] = fminf(mind2[j], __shfl_xor_sync(0xffffffffu, mind2[j], off));
            hbits[j] |= __shfl_xor_sync(0xffffffffu, hbits[j], off);
        }
    }

    if (l == 0) {
        float acc = 0.0f;
        #pragma unroll
        for (int j = 0; j < M; j++) {
            unsigned hw = (unsigned)(hbits[j] >> 32) | (unsigned)hbits[j];
            float md = sqrtf(mind2[j]);
            md = (hw & 0x80000000u) ? md : -md;   // sign set => intersect => outside
            acc += fmaxf(md + THRESH_, 0.0f);
        }
        sVal[w] = acc;
    }
    __syncthreads();

    // second-arriving block per (b,c) combines both halves into out.
    if (tid == 0) {
        float bsum = 0.0f;
        #pragma unroll
        for (int i = 0; i < WARPS; i++) bsum += sVal[i];
        g_scratch[idx * 2 + half] = bsum;
        __threadfence();
        unsigned old = atomicAdd(&g_tick[idx], 1u);
        if (old == 1u) {
            out[idx] = g_scratch[idx * 2] + g_scratch[idx * 2 + 1];
            g_tick[idx] = 0u;               // reset for next graph replay
        }
    }
}

extern "C" void kernel_launch(void* const* d_in, const int* in_sizes, int n_in,
                              void* d_out, int out_size) {
    const float* points      = (const float*)d_in[0];
    const float* road_bound  = (const float*)d_in[1];
    const float* centerlines = (const float*)d_in[2];
    float* out = (float*)d_out;
    (void)in_sizes; (void)n_in; (void)out_size;

    offroad_kernel<<<B_ * C_ * HALVES, THREADS>>>(points, road_bound, centerlines, out);
}

// round 13
// speedup vs baseline: 1.0125x; 1.0125x over previous
#include <cuda_runtime.h>
#include <cuda_bf16.h>
#include <math.h>

// Fixed shapes
#define B_ 32
#define C_ 6
#define T_ 64
#define K_ 8
#define N_ 128
#define NSEG 1016
#define NSEGP 1024
#define NCL 2048
#define NCLP2 1024             // candidate pairs
#define EPS_ 1e-6f
#define THRESH_ 0.5f
#define PAD_ 1e9f

#define THREADS 256
#define WARPS 8                // each warp = independent point group
#define M 4                    // points per warp
#define PTS_BLK (WARPS * M)    // 32
#define HALVES (T_ / PTS_BLK)  // 2
// grid = B*C*HALVES = 384

typedef unsigned long long u64;

__device__ float    g_scratch[B_ * C_ * 2];   // zero-init (.bss)
__device__ unsigned g_tick[B_ * C_];          // zero-init, reset after use

__device__ __forceinline__ u64 F2ADD(u64 a, u64 b) {
    u64 d; asm("add.rn.f32x2 %0,%1,%2;" : "=l"(d) : "l"(a), "l"(b)); return d;
}
__device__ __forceinline__ u64 F2SUB(u64 a, u64 b) {
    u64 d; asm("sub.rn.f32x2 %0,%1,%2;" : "=l"(d) : "l"(a), "l"(b)); return d;
}
__device__ __forceinline__ u64 F2MUL(u64 a, u64 b) {
    u64 d; asm("mul.rn.f32x2 %0,%1,%2;" : "=l"(d) : "l"(a), "l"(b)); return d;
}
__device__ __forceinline__ u64 F2FMA(u64 a, u64 b, u64 c) {
    u64 d; asm("fma.rn.f32x2 %0,%1,%2,%3;" : "=l"(d) : "l"(a), "l"(b), "l"(c)); return d;
}
__device__ __forceinline__ u64 F2PK(float lo, float hi) {
    u64 d; asm("mov.b64 %0,{%1,%2};" : "=l"(d) : "f"(lo), "f"(hi)); return d;
}
__device__ __forceinline__ void F2UP(u64 a, float& lo, float& hi) {
    asm("mov.b64 {%0,%1},%2;" : "=f"(lo), "=f"(hi) : "l"(a));
}

__global__ __launch_bounds__(THREADS, 3)
void offroad_kernel(const float* __restrict__ points,
                    const float* __restrict__ road_boundary,
                    const float* __restrict__ centerlines,
                    float* __restrict__ out) {
    __shared__ float4 sA[NSEGP];     // (-ax,-ax,-ay,-ay)
    __shared__ float4 sD[NSEGP];     // (-dx,-dx,-dy,-dy)
    __shared__ float  sI[NSEGP];     // negr = -1/(|d|^2+eps)
    __shared__ float4 sCl[NCLP2];    // (-qx0,-qx1,-qy0,-qy1) per cand pair
    __shared__ float2 sClh[NCLP2];   // (h0,h1) = 0.5*|q|^2 per pair
    __shared__ float  sVal[WARPS];

    const int bid = blockIdx.x;
    const int half = bid & 1;
    const int c = (bid >> 1) % C_;
    const int b = bid / (2 * C_);
    const int idx = b * C_ + c;
    const int tid = threadIdx.x;

    // ---- fill segments (padded with far-away inert unit segments) ----
    {
        const float2* rb = (const float2*)road_boundary + (size_t)b * K_ * N_;
        #pragma unroll
        for (int s0 = 0; s0 < NSEGP; s0 += THREADS) {
            int s = s0 + tid;
            float nax, nay, ndx, ndy;
            if (s < NSEG) {
                int k = s / (N_ - 1);
                int j = s - k * (N_ - 1);
                float2 a = rb[k * N_ + j];
                float2 e = rb[k * N_ + j + 1];
                nax = -a.x; nay = -a.y;
                ndx = a.x - e.x; ndy = a.y - e.y;
            } else {
                nax = -PAD_; nay = -PAD_;   // a = (PAD, PAD), d = (1,0): inert
                ndx = -1.0f; ndy = 0.0f;
            }
            sA[s] = make_float4(nax, nax, nay, nay);
            sD[s] = make_float4(ndx, ndx, ndy, ndy);
            sI[s] = -1.0f / (fmaf(ndx, ndx, ndy * ndy) + EPS_);
        }
    }
    // ---- fill centerlines (negated pair-SoA + half-norms) ----
    {
        const float4* cl4 = (const float4*)(centerlines + (size_t)b * NCL * 2);
        #pragma unroll
        for (int p0 = 0; p0 < NCLP2; p0 += THREADS) {
            int pi = p0 + tid;
            float4 v = cl4[pi];     // (q0x,q0y,q1x,q1y)
            sCl[pi] = make_float4(-v.x, -v.z, -v.y, -v.w);
            sClh[pi] = make_float2(0.5f * fmaf(v.x, v.x, v.y * v.y),
                                   0.5f * fmaf(v.z, v.z, v.w * v.w));
        }
    }
    __syncthreads();

    const int w = tid >> 5;     // warp = point group (0..7)
    const int l = tid & 31;

    float px[M], py[M];
    {
        const float2* pp = (const float2*)points +
            ((size_t)idx) * T_ + half * PTS_BLK + w * M;
        #pragma unroll
        for (int j = 0; j < M; j++) { float2 p = pp[j]; px[j] = p.x; py[j] = p.y; }
    }

    // ---- Phase A: argmin over candidate pairs (score = 0.5|q|^2 - p.q) ----
    u64 pxd[M], pyd[M];
    #pragma unroll
    for (int j = 0; j < M; j++) { pxd[j] = F2PK(px[j], px[j]); pyd[j] = F2PK(py[j], py[j]); }

    float sc[M]; int bp[M];     // best pair score / pair index
    #pragma unroll
    for (int j = 0; j < M; j++) { sc[j] = 3.4e38f; bp[j] = 0; }

    const u64* clh64 = (const u64*)sClh;
    #pragma unroll 8
    for (int it = 0; it < NCLP2 / 32; it++) {       // 32 iters
        int pi = l + it * 32;
        float4 nq = sCl[pi];
        u64 h2  = clh64[pi];
        u64 nqx = F2PK(nq.x, nq.y);
        u64 nqy = F2PK(nq.z, nq.w);
        #pragma unroll
        for (int j = 0; j < M; j++) {
            u64 s2 = F2FMA(pxd[j], nqx, F2FMA(pyd[j], nqy, h2));
            float s0, s1; F2UP(s2, s0, s1);
            float pmin = fminf(s0, s1);
            if (pmin < sc[j]) { sc[j] = pmin; bp[j] = pi; }
        }
    }
    #pragma unroll
    for (int off = 16; off; off >>= 1) {
        #pragma unroll
        for (int j = 0; j < M; j++) {
            float os = __shfl_xor_sync(0xffffffffu, sc[j], off);
            int   oi = __shfl_xor_sync(0xffffffffu, bp[j], off);
            if (os < sc[j] || (os == sc[j] && oi < bp[j])) { sc[j] = os; bp[j] = oi; }
        }
    }
    // resolve which half of the winning pair (recompute one packed score)
    float dax[M], day[M];
    #pragma unroll
    for (int j = 0; j < M; j++) {
        float4 nq = sCl[bp[j]];         // broadcast
        u64 h2 = clh64[bp[j]];
        u64 s2 = F2FMA(pxd[j], F2PK(nq.x, nq.y),
                 F2FMA(pyd[j], F2PK(nq.z, nq.w), h2));
        float s0, s1; F2UP(s2, s0, s1);
        bool h1 = (s1 < s0);            // tie -> half 0 (lower index)
        float nqx = h1 ? nq.y : nq.x;
        float nqy = h1 ? nq.w : nq.z;
        dax[j] = -nqx - px[j];          // qx - px
        day[j] = -nqy - py[j];
    }
    u64 px2[2]   = { F2PK(px[0], px[1]),   F2PK(px[2], px[3]) };
    u64 py2[2]   = { F2PK(py[0], py[1]),   F2PK(py[2], py[3]) };
    u64 dax2[2]  = { F2PK(dax[0], dax[1]), F2PK(dax[2], dax[3]) };
    u64 nday2[2] = { F2PK(-day[0], -day[1]), F2PK(-day[2], -day[3]) };
    const u64 neps2 = F2PK(-EPS_, -EPS_);

    // ---- Phase B: fused distance + intersection over segments ----
    float mind2[M];
    u64 hbits[2];
    #pragma unroll
    for (int j = 0; j < M; j++) mind2[j] = 3.4e38f;
    hbits[0] = 0ull; hbits[1] = 0ull;

    #pragma unroll 16
    for (int it = 0; it < NSEGP / 32; it++) {       // 32 iters
        int s = l + it * 32;
        float4 A = sA[s];
        float4 D = sD[s];
        float negr = sI[s];
        u64 nax2 = F2PK(A.x, A.y), nay2 = F2PK(A.z, A.w);
        u64 ndx2 = F2PK(D.x, D.y), ndy2 = F2PK(D.z, D.w);
        #pragma unroll
        for (int q = 0; q < 2; q++) {
            int j0 = 2 * q, j1 = 2 * q + 1;
            u64 v1x = F2ADD(px2[q], nax2);          // p - a
            u64 v1y = F2ADD(py2[q], nay2);
            u64 ndt = F2FMA(v1y, ndy2, F2MUL(v1x, ndx2));   // -(v1.d)
            float n0, n1; F2UP(ndt, n0, n1);
            float p0 = __saturatef(n0 * negr);       // FMUL.SAT
            float p1 = __saturatef(n1 * negr);
            u64 pr = F2PK(p0, p1);
            u64 ex = F2FMA(ndx2, pr, v1x);          // v1x - dx*pr
            u64 ey = F2FMA(ndy2, pr, v1y);
            u64 d2 = F2FMA(ey, ey, F2MUL(ex, ex));
            float d20, d21; F2UP(d2, d20, d21);
            mind2[j0] = fminf(mind2[j0], d20);
            mind2[j1] = fminf(mind2[j1], d21);
            // nw = -(cross(da,db)+eps); c1 = cross(da,v1); c2 = cross(db,v1)
            u64 nw = F2FMA(nday2[q], ndx2, F2FMA(dax2[q], ndy2, neps2));
            u64 c1 = F2FMA(dax2[q], v1y, F2MUL(nday2[q], v1x));
            u64 c2 = F2SUB(F2MUL(ndy2, v1x), F2MUL(ndx2, v1y));
            u64 s1 = F2MUL(c1, F2ADD(c1, nw));      // half-hit iff sign set
            u64 s2 = F2MUL(c2, F2ADD(c2, nw));
            hbits[q] |= (s1 & s2);                  // LOP3 sign-AND, OR-accumulate
        }
    }
    #pragma unroll
    for (int off = 16; off; off >>= 1) {
        #pragma unroll
        for (int j = 0; j < M; j++)
            mind2[j] = fminf(mind2[j], __shfl_xor_sync(0xffffffffu, mind2[j], off));
        #pragma unroll
        for (int q = 0; q < 2; q++)
            hbits[q] |= __shfl_xor_sync(0xffffffffu, hbits[q], off);
    }

    if (l == 0) {
        float acc = 0.0f;
        #pragma unroll
        for (int j = 0; j < M; j++) {
            u64 hb = hbits[j >> 1];
            unsigned hw = (j & 1) ? (unsigned)(hb >> 32) : (unsigned)hb;
            float md = sqrtf(mind2[j]);
            md = (hw & 0x80000000u) ? md : -md;   // sign set => intersect => outside
            acc += fmaxf(md + THRESH_, 0.0f);
        }
        sVal[w] = acc;
    }
    __syncthreads();

    // second-arriving block per (b,c) combines both halves into out.
    if (tid == 0) {
        float bsum = 0.0f;
        #pragma unroll
        for (int i = 0; i < WARPS; i++) bsum += sVal[i];
        g_scratch[idx * 2 + half] = bsum;
        __threadfence();
        unsigned old = atomicAdd(&g_tick[idx], 1u);
        if (old == 1u) {
            out[idx] = g_scratch[idx * 2] + g_scratch[idx * 2 + 1];
            g_tick[idx] = 0u;               // reset for next graph replay
        }
    }
}

extern "C" void kernel_launch(void* const* d_in, const int* in_sizes, int n_in,
                              void* d_out, int out_size) {
    const float* points      = (const float*)d_in[0];
    const float* road_bound  = (const float*)d_in[1];
    const float* centerlines = (const float*)d_in[2];
    float* out = (float*)d_out;
    (void)in_sizes; (void)n_in; (void)out_size;

    offroad_kernel<<<B_ * C_ * HALVES, THREADS>>>(points, road_bound, centerlines, out);
}